// round 2
// baseline (speedup 1.0000x reference)
#include <cuda_runtime.h>
#include <math.h>

#define NB 4
#define NT 2048
#define NC 1024
#define NH 16
#define ND 64
#define NM (NB*NT)           // 8192 rows

// Scratch (allocation-free): ~128 MB of __device__ globals
__device__ float g_Q[NB*NH*NT*ND];
__device__ float g_K[NB*NH*NT*ND];
__device__ float g_V[NB*NH*NT*ND];
__device__ float g_AO[(size_t)NM*NC];

// ---------------------------------------------------------------------------
// Tiled SGEMM: BM=BN=128, BK=16, 256 threads, 8x8 per thread
// ---------------------------------------------------------------------------
#define BM 128
#define BN 128
#define BK 16

__global__ __launch_bounds__(256) void qkv_gemm_kernel(
    const float* __restrict__ X, const float* __restrict__ W)
{
    __shared__ float As[BK][BM];
    __shared__ float Bs[BK][BN];
    const int tid = threadIdx.x;
    const int tx = tid & 15, ty = tid >> 4;
    const int rowA0 = blockIdx.y * BM;
    const int colB0 = blockIdx.x * BN;

    float acc[8][8];
    #pragma unroll
    for (int i = 0; i < 8; i++)
        #pragma unroll
        for (int j = 0; j < 8; j++) acc[i][j] = 0.f;

    const int arow = tid >> 2;
    const int acol = (tid & 3) << 2;
    const int brow = tid >> 4;
    const int bcol = (tid & 15) << 2;

    for (int k0 = 0; k0 < NC; k0 += BK) {
        #pragma unroll
        for (int r = 0; r < 2; r++) {
            int row = arow + r * 64;
            float4 v = *(const float4*)&X[(size_t)(rowA0 + row) * NC + k0 + acol];
            As[acol+0][row] = v.x; As[acol+1][row] = v.y;
            As[acol+2][row] = v.z; As[acol+3][row] = v.w;
        }
        #pragma unroll
        for (int r = 0; r < 2; r++) {
            int col = bcol + r * 64;
            *(float4*)&Bs[brow][col] =
                *(const float4*)&W[(size_t)(k0 + brow) * (3*NC) + colB0 + col];
        }
        __syncthreads();
        #pragma unroll
        for (int k = 0; k < BK; k++) {
            float a[8], b[8];
            *(float4*)&a[0] = *(float4*)&As[k][ty*8];
            *(float4*)&a[4] = *(float4*)&As[k][ty*8+4];
            *(float4*)&b[0] = *(float4*)&Bs[k][tx*8];
            *(float4*)&b[4] = *(float4*)&Bs[k][tx*8+4];
            #pragma unroll
            for (int i = 0; i < 8; i++)
                #pragma unroll
                for (int j = 0; j < 8; j++)
                    acc[i][j] += a[i] * b[j];
        }
        __syncthreads();
    }

    // Scatter epilogue into Q/K/V in [B,H,T,D] layout
    #pragma unroll
    for (int i = 0; i < 8; i++) {
        int row = rowA0 + ty*8 + i;
        int b = row >> 11;            // row / 2048
        int t = row & (NT - 1);
        #pragma unroll
        for (int j4 = 0; j4 < 2; j4++) {
            int col = colB0 + tx*8 + j4*4;
            int which = col >> 10;
            int h = (col >> 6) & 15;
            int d = col & 63;
            float* dst = (which == 0) ? g_Q : (which == 1) ? g_K : g_V;
            float4 v = make_float4(acc[i][j4*4+0], acc[i][j4*4+1],
                                   acc[i][j4*4+2], acc[i][j4*4+3]);
            *(float4*)&dst[(((size_t)(b*NH + h) * NT + t) << 6) + d] = v;
        }
    }
}

__global__ __launch_bounds__(256) void out_gemm_kernel(
    const float* __restrict__ W, float* __restrict__ OUT)
{
    __shared__ float As[BK][BM];
    __shared__ float Bs[BK][BN];
    const int tid = threadIdx.x;
    const int tx = tid & 15, ty = tid >> 4;
    const int rowA0 = blockIdx.y * BM;
    const int colB0 = blockIdx.x * BN;

    float acc[8][8];
    #pragma unroll
    for (int i = 0; i < 8; i++)
        #pragma unroll
        for (int j = 0; j < 8; j++) acc[i][j] = 0.f;

    const int arow = tid >> 2;
    const int acol = (tid & 3) << 2;
    const int brow = tid >> 4;
    const int bcol = (tid & 15) << 2;

    for (int k0 = 0; k0 < NC; k0 += BK) {
        #pragma unroll
        for (int r = 0; r < 2; r++) {
            int row = arow + r * 64;
            float4 v = *(const float4*)&g_AO[(size_t)(rowA0 + row) * NC + k0 + acol];
            As[acol+0][row] = v.x; As[acol+1][row] = v.y;
            As[acol+2][row] = v.z; As[acol+3][row] = v.w;
        }
        #pragma unroll
        for (int r = 0; r < 2; r++) {
            int col = bcol + r * 64;
            *(float4*)&Bs[brow][col] =
                *(const float4*)&W[(size_t)(k0 + brow) * NC + colB0 + col];
        }
        __syncthreads();
        #pragma unroll
        for (int k = 0; k < BK; k++) {
            float a[8], b[8];
            *(float4*)&a[0] = *(float4*)&As[k][ty*8];
            *(float4*)&a[4] = *(float4*)&As[k][ty*8+4];
            *(float4*)&b[0] = *(float4*)&Bs[k][tx*8];
            *(float4*)&b[4] = *(float4*)&Bs[k][tx*8+4];
            #pragma unroll
            for (int i = 0; i < 8; i++)
                #pragma unroll
                for (int j = 0; j < 8; j++)
                    acc[i][j] += a[i] * b[j];
        }
        __syncthreads();
    }

    #pragma unroll
    for (int i = 0; i < 8; i++) {
        size_t row = rowA0 + ty*8 + i;
        #pragma unroll
        for (int j4 = 0; j4 < 2; j4++) {
            int col = colB0 + tx*8 + j4*4;
            float4 v = make_float4(acc[i][j4*4+0], acc[i][j4*4+1],
                                   acc[i][j4*4+2], acc[i][j4*4+3]);
            *(float4*)&OUT[row * NC + col] = v;
        }
    }
}

// ---------------------------------------------------------------------------
// Flash attention: one block per (q-tile of 64, b*h). 256 threads, 4x4 tiles.
// Smem: sQ^T [64][68], sK^T [64][68] (reused as P^T), sV [64][68]
// ---------------------------------------------------------------------------
#define PAD 68
#define ATTN_SMEM (3 * ND * PAD * sizeof(float))

__global__ __launch_bounds__(256) void attn_kernel()
{
    extern __shared__ float sm[];
    float* sQ = sm;                 // sQ[d*PAD + r]
    float* sK = sm + ND*PAD;        // sK[d*PAD + c]; later P^T[c*PAD + r]
    float* sV = sm + 2*ND*PAD;      // sV[c*PAD + d]

    const int tid = threadIdx.x;
    const int tx = tid & 15, ty = tid >> 4;
    const int qt = blockIdx.x;
    const int bh = blockIdx.y;
    const int b = bh >> 4, h = bh & 15;

    const float* Qg  = g_Q + ((size_t)bh * NT + qt*64) * ND;
    const float* Kg0 = g_K + (size_t)bh * NT * ND;
    const float* Vg0 = g_V + (size_t)bh * NT * ND;

    // Load Q tile transposed (d-major)
    #pragma unroll
    for (int q = 0; q < 4; q++) {
        int f = tid + q*256;
        int row = f >> 4;
        int c4 = (f & 15) << 2;
        float4 v = *(const float4*)&Qg[row*ND + c4];
        sQ[(c4+0)*PAD + row] = v.x;
        sQ[(c4+1)*PAD + row] = v.y;
        sQ[(c4+2)*PAD + row] = v.z;
        sQ[(c4+3)*PAD + row] = v.w;
    }

    float m_i[4], l_i[4], o[4][4];
    #pragma unroll
    for (int i = 0; i < 4; i++) {
        m_i[i] = -1e30f; l_i[i] = 0.f;
        #pragma unroll
        for (int j = 0; j < 4; j++) o[i][j] = 0.f;
    }

    const int q0 = qt * 64;

    for (int jt = 0; jt <= qt; jt++) {
        const float* Kg = Kg0 + (size_t)jt*64*ND;
        const float* Vg = Vg0 + (size_t)jt*64*ND;
        __syncthreads();   // previous PV done before overwriting sK/sV (and Q visible)
        #pragma unroll
        for (int q = 0; q < 4; q++) {
            int f = tid + q*256;
            int row = f >> 4;
            int c4 = (f & 15) << 2;
            float4 v = *(const float4*)&Kg[row*ND + c4];
            sK[(c4+0)*PAD + row] = v.x;
            sK[(c4+1)*PAD + row] = v.y;
            sK[(c4+2)*PAD + row] = v.z;
            sK[(c4+3)*PAD + row] = v.w;
            float4 w = *(const float4*)&Vg[row*ND + c4];
            *(float4*)&sV[row*PAD + c4] = w;
        }
        __syncthreads();

        // S = Q K^T
        float s[4][4];
        #pragma unroll
        for (int i = 0; i < 4; i++)
            #pragma unroll
            for (int j = 0; j < 4; j++) s[i][j] = 0.f;

        for (int d = 0; d < ND; d++) {
            float4 a  = *(float4*)&sQ[d*PAD + ty*4];
            float4 bb = *(float4*)&sK[d*PAD + tx*4];
            float av[4] = {a.x, a.y, a.z, a.w};
            float bv[4] = {bb.x, bb.y, bb.z, bb.w};
            #pragma unroll
            for (int i = 0; i < 4; i++)
                #pragma unroll
                for (int j = 0; j < 4; j++)
                    s[i][j] += av[i] * bv[j];
        }

        // scale + causal mask
        #pragma unroll
        for (int i = 0; i < 4; i++) {
            int qi = q0 + ty*4 + i;
            #pragma unroll
            for (int j = 0; j < 4; j++) {
                int kj = jt*64 + tx*4 + j;
                s[i][j] = (kj <= qi) ? s[i][j] * 0.125f : -1e30f;
            }
        }

        // online softmax (row spread across 16 lanes, 4 each)
        #pragma unroll
        for (int i = 0; i < 4; i++) {
            float mx = fmaxf(fmaxf(s[i][0], s[i][1]), fmaxf(s[i][2], s[i][3]));
            #pragma unroll
            for (int off = 8; off >= 1; off >>= 1)
                mx = fmaxf(mx, __shfl_xor_sync(0xffffffffu, mx, off));
            float newm = fmaxf(m_i[i], mx);
            float corr = __expf(m_i[i] - newm);
            m_i[i] = newm;
            float ps = 0.f;
            #pragma unroll
            for (int j = 0; j < 4; j++) {
                s[i][j] = __expf(s[i][j] - newm);
                ps += s[i][j];
            }
            #pragma unroll
            for (int off = 8; off >= 1; off >>= 1)
                ps += __shfl_xor_sync(0xffffffffu, ps, off);
            l_i[i] = l_i[i] * corr + ps;
            #pragma unroll
            for (int j = 0; j < 4; j++) o[i][j] *= corr;
        }

        __syncthreads();     // everyone done reading sK as K
        // write P^T into sK: P^T[c][r]
        #pragma unroll
        for (int i = 0; i < 4; i++)
            #pragma unroll
            for (int j = 0; j < 4; j++)
                sK[(tx*4 + j)*PAD + ty*4 + i] = s[i][j];
        __syncthreads();

        // O += P V
        for (int c = 0; c < 64; c++) {
            float4 a  = *(float4*)&sK[c*PAD + ty*4];
            float4 bv = *(float4*)&sV[c*PAD + tx*4];
            float av[4] = {a.x, a.y, a.z, a.w};
            float vv[4] = {bv.x, bv.y, bv.z, bv.w};
            #pragma unroll
            for (int i = 0; i < 4; i++)
                #pragma unroll
                for (int j = 0; j < 4; j++)
                    o[i][j] += av[i] * vv[j];
        }
    }

    // normalize + write to g_AO in [B,T,C] layout
    #pragma unroll
    for (int i = 0; i < 4; i++) {
        int qi = q0 + ty*4 + i;
        float inv = 1.0f / l_i[i];
        float4 v = make_float4(o[i][0]*inv, o[i][1]*inv, o[i][2]*inv, o[i][3]*inv);
        *(float4*)&g_AO[(size_t)(b*NT + qi) * NC + h*ND + tx*4] = v;
    }
}

// ---------------------------------------------------------------------------
extern "C" void kernel_launch(void* const* d_in, const int* in_sizes, int n_in,
                              void* d_out, int out_size)
{
    const float* x    = (const float*)d_in[0];
    const float* Wqkv = (const float*)d_in[1];
    const float* Wout = (const float*)d_in[2];
    // d_in[3] (mask) is deterministic tril -> causal masking hard-coded
    float* out = (float*)d_out;

    cudaFuncSetAttribute(attn_kernel,
                         cudaFuncAttributeMaxDynamicSharedMemorySize,
                         (int)ATTN_SMEM);

    dim3 g1(3*NC / BN, NM / BM);     // 24 x 64
    qkv_gemm_kernel<<<g1, 256>>>(x, Wqkv);

    dim3 ga(NT / 64, NB * NH);       // 32 x 64
    attn_kernel<<<ga, 256, ATTN_SMEM>>>();

    dim3 g2(NC / BN, NM / BM);       // 8 x 64
    out_gemm_kernel<<<g2, 256>>>(Wout, out);
}

// round 3
// speedup vs baseline: 2.9454x; 2.9454x over previous
#include <cuda_runtime.h>
#include <cstdint>

#define NB 4
#define NT 2048
#define NC 1024
#define NH 16
#define ND 64
#define NM (NB*NT)           // 8192 rows

// Scratch (allocation-free)
__device__ float g_Q[(size_t)NB*NH*NT*ND];
__device__ float g_K[(size_t)NB*NH*NT*ND];
__device__ float g_V[(size_t)NB*NH*NT*ND];
__device__ float g_AO[(size_t)NM*NC];

__device__ __forceinline__ uint32_t f2tf32(float f) {
    uint32_t r; asm("cvt.rna.tf32.f32 %0, %1;" : "=r"(r) : "f"(f)); return r;
}

__device__ __forceinline__ void mma_tf32(float* d, const uint32_t* a, const uint32_t* b) {
    asm volatile(
        "mma.sync.aligned.m16n8k8.row.col.f32.tf32.tf32.f32 "
        "{%0,%1,%2,%3}, {%4,%5,%6,%7}, {%8,%9}, {%0,%1,%2,%3};\n"
        : "+f"(d[0]), "+f"(d[1]), "+f"(d[2]), "+f"(d[3])
        : "r"(a[0]), "r"(a[1]), "r"(a[2]), "r"(a[3]), "r"(b[0]), "r"(b[1]));
}

// ---------------------------------------------------------------------------
// tf32 tensor-core GEMM: 128x128 block, BK=16, 256 threads (8 warps 4x2),
// warp tile 32x64 (m-frags 2, n-frags 8).
// As[m][k] stride 20 (==4 mod 32): conflict-free A-fragment loads.
// Bs[k][n] stride 136 (==8 mod 32): conflict-free B-fragment loads.
// ---------------------------------------------------------------------------
template<int LDB, bool SCATTER, bool USE_GAO>
__global__ __launch_bounds__(256) void gemm_tf32(
    const float* __restrict__ Ain, const float* __restrict__ B, float* __restrict__ C)
{
    __shared__ uint32_t As[128][20];
    __shared__ uint32_t Bs[16][136];

    const float* __restrict__ A = USE_GAO ? (const float*)g_AO : Ain;

    const int tid  = threadIdx.x;
    const int lane = tid & 31, wid = tid >> 5;
    const int wm = (wid & 3) * 32, wn = (wid >> 2) * 64;
    const int g = lane >> 2, q4 = lane & 3;
    const int rowA0 = blockIdx.y * 128, colB0 = blockIdx.x * 128;

    float acc[2][8][4];
    #pragma unroll
    for (int i = 0; i < 2; i++)
        #pragma unroll
        for (int j = 0; j < 8; j++)
            #pragma unroll
            for (int k = 0; k < 4; k++) acc[i][j][k] = 0.f;

    const int ar = tid >> 2, ac = (tid & 3) << 2;   // A: rows ar, ar+64; k-offs ac
    const int br = tid >> 5, bc = (tid & 31) << 2;  // B: rows br, br+8; col bc

    for (int k0 = 0; k0 < NC; k0 += 16) {
        #pragma unroll
        for (int r = 0; r < 2; r++) {
            float4 v = *(const float4*)&A[(size_t)(rowA0 + ar + r*64) * NC + k0 + ac];
            uint32_t* p = &As[ar + r*64][ac];
            p[0] = f2tf32(v.x); p[1] = f2tf32(v.y);
            p[2] = f2tf32(v.z); p[3] = f2tf32(v.w);
        }
        #pragma unroll
        for (int r = 0; r < 2; r++) {
            float4 v = *(const float4*)&B[(size_t)(k0 + br + r*8) * LDB + colB0 + bc];
            uint32_t* p = &Bs[br + r*8][bc];
            p[0] = f2tf32(v.x); p[1] = f2tf32(v.y);
            p[2] = f2tf32(v.z); p[3] = f2tf32(v.w);
        }
        __syncthreads();

        #pragma unroll
        for (int kk = 0; kk < 2; kk++) {
            const int kb = kk * 8;
            uint32_t a[2][4];
            #pragma unroll
            for (int i = 0; i < 2; i++) {
                int row = wm + i*16 + g;
                a[i][0] = As[row    ][kb + q4];
                a[i][1] = As[row + 8][kb + q4];
                a[i][2] = As[row    ][kb + q4 + 4];
                a[i][3] = As[row + 8][kb + q4 + 4];
            }
            #pragma unroll
            for (int j = 0; j < 8; j++) {
                uint32_t b2[2];
                int col = wn + j*8 + g;
                b2[0] = Bs[kb + q4    ][col];
                b2[1] = Bs[kb + q4 + 4][col];
                mma_tf32(acc[0][j], a[0], b2);
                mma_tf32(acc[1][j], a[1], b2);
            }
        }
        __syncthreads();
    }

    // epilogue: C frag c0/c1 at (row, 2*q4 +{0,1}), c2/c3 at (row+8, ...)
    #pragma unroll
    for (int i = 0; i < 2; i++) {
        #pragma unroll
        for (int j = 0; j < 8; j++) {
            #pragma unroll
            for (int half = 0; half < 2; half++) {
                int row = rowA0 + wm + i*16 + g + half*8;
                int col = colB0 + wn + j*8 + 2*q4;
                float2 v = make_float2(acc[i][j][half*2], acc[i][j][half*2+1]);
                if (SCATTER) {
                    int b = row >> 11, t = row & (NT - 1);
                    int which = col >> 10, h = (col >> 6) & 15, d = col & 63;
                    float* dst = (which == 0) ? g_Q : (which == 1) ? g_K : g_V;
                    *(float2*)&dst[(((size_t)(b*NH + h) * NT + t) << 6) + d] = v;
                } else {
                    *(float2*)&C[(size_t)row * NC + col] = v;
                }
            }
        }
    }
}

// ---------------------------------------------------------------------------
// Flash attention on tensor cores. 128 threads (4 warps), q-tile 64 rows,
// warp w owns rows [w*16, w*16+16). All mma tf32 m16n8k8.
// sQP [64][68]: Q (consumed into regs) then reused for P.
// sK  [64][68], sV [64][72] — strides chosen conflict-free per fragment.
// ---------------------------------------------------------------------------
#define SQS 68
#define SVS 72
#define ATTN_SMEM ((2*64*SQS + 64*SVS) * 4)

__global__ __launch_bounds__(128) void attn_tc()
{
    extern __shared__ uint32_t sm[];
    uint32_t* sQP = sm;              // [64][68]
    uint32_t* sK  = sm + 64*SQS;     // [64][68]
    uint32_t* sV  = sm + 2*64*SQS;   // [64][72]

    const int tid = threadIdx.x;
    const int lane = tid & 31, w = tid >> 5;
    const int g = lane >> 2, q4 = lane & 3;
    const int qt = blockIdx.x, bh = blockIdx.y;
    const int b = bh >> 4, h = bh & 15;
    const int q0 = qt * 64;

    const float* Qg  = g_Q + ((size_t)bh * NT + q0) * ND;
    const float* Kg0 = g_K + (size_t)bh * NT * ND;
    const float* Vg0 = g_V + (size_t)bh * NT * ND;

    // cooperative load of Q (pre-scaled by 1/sqrt(D)=0.125) into smem
    #pragma unroll
    for (int i = 0; i < 8; i++) {
        int idx = tid + i*128;
        int row = idx >> 4, c4 = (idx & 15) << 2;
        float4 v = *(const float4*)&Qg[row*ND + c4];
        uint32_t* p = &sQP[row*SQS + c4];
        p[0] = f2tf32(v.x * 0.125f); p[1] = f2tf32(v.y * 0.125f);
        p[2] = f2tf32(v.z * 0.125f); p[3] = f2tf32(v.w * 0.125f);
    }
    __syncthreads();

    // Q A-fragments (warp-local rows) into registers; frees sQP for P
    uint32_t qf[8][4];
    {
        int row = w*16 + g;
        #pragma unroll
        for (int kf = 0; kf < 8; kf++) {
            int col = kf*8 + q4;
            qf[kf][0] = sQP[row*SQS + col];
            qf[kf][1] = sQP[(row+8)*SQS + col];
            qf[kf][2] = sQP[row*SQS + col + 4];
            qf[kf][3] = sQP[(row+8)*SQS + col + 4];
        }
    }

    float o[8][4];
    #pragma unroll
    for (int i = 0; i < 8; i++)
        #pragma unroll
        for (int j = 0; j < 4; j++) o[i][j] = 0.f;
    float m0 = -1e30f, m1 = -1e30f, l0 = 0.f, l1 = 0.f;

    for (int jt = 0; jt <= qt; jt++) {
        __syncthreads();   // all PV reads of prev sK/sV done (also covers qf reads)
        const float* Kg = Kg0 + (size_t)jt*64*ND;
        const float* Vg = Vg0 + (size_t)jt*64*ND;
        #pragma unroll
        for (int i = 0; i < 8; i++) {
            int idx = tid + i*128;
            int row = idx >> 4, c4 = (idx & 15) << 2;
            float4 v = *(const float4*)&Kg[row*ND + c4];
            uint32_t* p = &sK[row*SQS + c4];
            p[0] = f2tf32(v.x); p[1] = f2tf32(v.y);
            p[2] = f2tf32(v.z); p[3] = f2tf32(v.w);
            float4 u = *(const float4*)&Vg[row*ND + c4];
            uint32_t* pv = &sV[row*SVS + c4];
            pv[0] = f2tf32(u.x); pv[1] = f2tf32(u.y);
            pv[2] = f2tf32(u.z); pv[3] = f2tf32(u.w);
        }
        __syncthreads();

        // S = Q K^T   (B frag: b0 = K[nf*8+g][kf*8+q4], b1 = +4 in d)
        float s[8][4];
        #pragma unroll
        for (int i = 0; i < 8; i++)
            #pragma unroll
            for (int j = 0; j < 4; j++) s[i][j] = 0.f;
        #pragma unroll
        for (int kf = 0; kf < 8; kf++) {
            #pragma unroll
            for (int nf = 0; nf < 8; nf++) {
                uint32_t b2[2];
                b2[0] = sK[(nf*8 + g)*SQS + kf*8 + q4];
                b2[1] = sK[(nf*8 + g)*SQS + kf*8 + q4 + 4];
                mma_tf32(s[nf], qf[kf], b2);
            }
        }

        // causal mask (only the diagonal tile needs it)
        if (jt == qt) {
            int r0 = w*16 + g, r1 = r0 + 8;
            #pragma unroll
            for (int nf = 0; nf < 8; nf++) {
                int c = nf*8 + 2*q4;
                if (c     > r0) s[nf][0] = -1e30f;
                if (c + 1 > r0) s[nf][1] = -1e30f;
                if (c     > r1) s[nf][2] = -1e30f;
                if (c + 1 > r1) s[nf][3] = -1e30f;
            }
        }

        // online softmax: thread holds 2 rows (r0, r0+8), 16 cols each
        float mx0 = -1e30f, mx1 = -1e30f;
        #pragma unroll
        for (int nf = 0; nf < 8; nf++) {
            mx0 = fmaxf(mx0, fmaxf(s[nf][0], s[nf][1]));
            mx1 = fmaxf(mx1, fmaxf(s[nf][2], s[nf][3]));
        }
        mx0 = fmaxf(mx0, __shfl_xor_sync(0xffffffffu, mx0, 1));
        mx0 = fmaxf(mx0, __shfl_xor_sync(0xffffffffu, mx0, 2));
        mx1 = fmaxf(mx1, __shfl_xor_sync(0xffffffffu, mx1, 1));
        mx1 = fmaxf(mx1, __shfl_xor_sync(0xffffffffu, mx1, 2));
        float nm0 = fmaxf(m0, mx0), nm1 = fmaxf(m1, mx1);
        float c0 = __expf(m0 - nm0), c1 = __expf(m1 - nm1);
        m0 = nm0; m1 = nm1;
        float ps0 = 0.f, ps1 = 0.f;
        #pragma unroll
        for (int nf = 0; nf < 8; nf++) {
            s[nf][0] = __expf(s[nf][0] - nm0);
            s[nf][1] = __expf(s[nf][1] - nm0);
            s[nf][2] = __expf(s[nf][2] - nm1);
            s[nf][3] = __expf(s[nf][3] - nm1);
            ps0 += s[nf][0] + s[nf][1];
            ps1 += s[nf][2] + s[nf][3];
        }
        ps0 += __shfl_xor_sync(0xffffffffu, ps0, 1);
        ps0 += __shfl_xor_sync(0xffffffffu, ps0, 2);
        ps1 += __shfl_xor_sync(0xffffffffu, ps1, 1);
        ps1 += __shfl_xor_sync(0xffffffffu, ps1, 2);
        l0 = l0 * c0 + ps0;
        l1 = l1 * c1 + ps1;
        #pragma unroll
        for (int df = 0; df < 8; df++) {
            o[df][0] *= c0; o[df][1] *= c0;
            o[df][2] *= c1; o[df][3] *= c1;
        }

        // store P into warp-local rows of sQP (A-fragment source)
        __syncwarp();
        {
            int r0 = w*16 + g;
            #pragma unroll
            for (int nf = 0; nf < 8; nf++) {
                int c = nf*8 + 2*q4;
                sQP[r0*SQS + c]       = f2tf32(s[nf][0]);
                sQP[r0*SQS + c + 1]   = f2tf32(s[nf][1]);
                sQP[(r0+8)*SQS + c]   = f2tf32(s[nf][2]);
                sQP[(r0+8)*SQS + c+1] = f2tf32(s[nf][3]);
            }
        }
        __syncwarp();

        // O += P V   (A frag from sQP, B frag: b0 = V[kf*8+q4][df*8+g])
        #pragma unroll
        for (int kf = 0; kf < 8; kf++) {
            uint32_t a[4];
            int row = w*16 + g;
            a[0] = sQP[row*SQS + kf*8 + q4];
            a[1] = sQP[(row+8)*SQS + kf*8 + q4];
            a[2] = sQP[row*SQS + kf*8 + q4 + 4];
            a[3] = sQP[(row+8)*SQS + kf*8 + q4 + 4];
            #pragma unroll
            for (int df = 0; df < 8; df++) {
                uint32_t b2[2];
                b2[0] = sV[(kf*8 + q4)*SVS + df*8 + g];
                b2[1] = sV[(kf*8 + q4 + 4)*SVS + df*8 + g];
                mma_tf32(o[df], a, b2);
            }
        }
    }

    // normalize and write to g_AO [B,T,C]
    float i0 = 1.f / l0, i1 = 1.f / l1;
    int r0 = q0 + w*16 + g;
    #pragma unroll
    for (int df = 0; df < 8; df++) {
        int col = h*ND + df*8 + 2*q4;
        *(float2*)&g_AO[(size_t)(b*NT + r0) * NC + col] =
            make_float2(o[df][0]*i0, o[df][1]*i0);
        *(float2*)&g_AO[(size_t)(b*NT + r0 + 8) * NC + col] =
            make_float2(o[df][2]*i1, o[df][3]*i1);
    }
}

// ---------------------------------------------------------------------------
extern "C" void kernel_launch(void* const* d_in, const int* in_sizes, int n_in,
                              void* d_out, int out_size)
{
    const float* x    = (const float*)d_in[0];
    const float* Wqkv = (const float*)d_in[1];
    const float* Wout = (const float*)d_in[2];
    // mask is deterministic tril -> hard-coded causal
    float* out = (float*)d_out;

    cudaFuncSetAttribute(attn_tc,
                         cudaFuncAttributeMaxDynamicSharedMemorySize,
                         ATTN_SMEM);

    dim3 g1(3*NC / 128, NM / 128);   // 24 x 64
    gemm_tf32<3*NC, true, false><<<g1, 256>>>(x, Wqkv, nullptr);

    dim3 ga(NT / 64, NB * NH);       // 32 x 64
    attn_tc<<<ga, 128, ATTN_SMEM>>>();

    dim3 g2(NC / 128, NM / 128);     // 8 x 64
    gemm_tf32<NC, false, true><<<g2, 256>>>(nullptr, Wout, out);
}

// round 5
// speedup vs baseline: 3.2040x; 1.0878x over previous
#include <cuda_runtime.h>
#include <cstdint>

#define NB 4
#define NT 2048
#define NC 1024
#define NH 16
#define ND 64
#define NM (NB*NT)           // 8192 rows

// Scratch (allocation-free). Q/K/V hold tf32 bit patterns (Q pre-scaled).
__device__ uint32_t g_Q[(size_t)NB*NH*NT*ND];
__device__ uint32_t g_K[(size_t)NB*NH*NT*ND];
__device__ uint32_t g_V[(size_t)NB*NH*NT*ND];
__device__ float    g_AO[(size_t)NM*NC];

// ===========================================================================
// helpers
// ===========================================================================
__device__ __forceinline__ uint32_t smem_to_u32(const void* p) {
    uint32_t a;
    asm("{ .reg .u64 t; cvta.to.shared.u64 t, %1; cvt.u32.u64 %0, t; }"
        : "=r"(a) : "l"(p));
    return a;
}
__device__ __forceinline__ uint32_t f2tf32(float f) {
    uint32_t r; asm("cvt.rna.tf32.f32 %0, %1;" : "=r"(r) : "f"(f)); return r;
}
__device__ __forceinline__ void mma_tf32(float* d, const uint32_t* a, const uint32_t* b) {
    asm volatile(
        "mma.sync.aligned.m16n8k8.row.col.f32.tf32.tf32.f32 "
        "{%0,%1,%2,%3}, {%4,%5,%6,%7}, {%8,%9}, {%0,%1,%2,%3};\n"
        : "+f"(d[0]), "+f"(d[1]), "+f"(d[2]), "+f"(d[3])
        : "r"(a[0]), "r"(a[1]), "r"(a[2]), "r"(a[3]), "r"(b[0]), "r"(b[1]));
}
#define CP_ASYNC16(dst, src) \
    asm volatile("cp.async.cg.shared.global [%0], [%1], 16;" \
        :: "r"(dst), "l"(src) : "memory")
#define CP_COMMIT() asm volatile("cp.async.commit_group;" ::: "memory")
#define CP_WAIT1()  asm volatile("cp.async.wait_group 1;" ::: "memory")
#define CP_WAIT0()  asm volatile("cp.async.wait_group 0;" ::: "memory")

// ===========================================================================
// tf32 mma.sync GEMM, cp.async 3-stage pipeline.
// Block 128x128, BK=16, 256 threads (8 warps 4x2), warp tile 32x64.
// smem per stage: A 128x16 fp32 (swizzle k^(((row>>1)&3)<<2)), 8KB
//                 B  16x128 fp32 (swizzle n^((k&3)<<3)),       8KB
// ===========================================================================
#define GSTAGES 3
#define GEMM_SMEM (GSTAGES * 16384)

template<int LDB, bool SCATTER, bool USE_GAO>
__global__ __launch_bounds__(256) void gemm_tc(
    const float* __restrict__ Ain, const float* __restrict__ B, float* __restrict__ C)
{
    extern __shared__ float smf[];
    const uint32_t sb = smem_to_u32(smf);
    const float* __restrict__ A = USE_GAO ? (const float*)g_AO : Ain;

    const int tid  = threadIdx.x;
    const int lane = tid & 31, wid = tid >> 5;
    const int wm = (wid & 3) * 32, wn = (wid >> 2) * 64;
    const int g = lane >> 2, q4 = lane & 3;
    const int rowA0 = blockIdx.y * 128, colB0 = blockIdx.x * 128;

    const int la_row = tid >> 2, la_k4 = (tid & 3) << 2;
    const int lb_k   = tid >> 5, lb_n4 = (tid & 31) << 2;

    float acc[2][8][4];
    #pragma unroll
    for (int i = 0; i < 2; i++)
        #pragma unroll
        for (int j = 0; j < 8; j++)
            #pragma unroll
            for (int k = 0; k < 4; k++) acc[i][j][k] = 0.f;

    constexpr int NIT = NC / 16;

    auto issue = [&](int s) {
        const uint32_t bufA = sb + (s % GSTAGES) * 16384;
        const uint32_t bufB = bufA + 8192;
        const int k0 = s * 16;
        #pragma unroll
        for (int r = 0; r < 2; r++) {
            int row = la_row + r*64;
            uint32_t d = bufA + row*64 + ((la_k4 ^ (((row>>1)&3)<<2)) << 2);
            CP_ASYNC16(d, &A[(size_t)(rowA0 + row) * NC + k0 + la_k4]);
        }
        #pragma unroll
        for (int r = 0; r < 2; r++) {
            int k = lb_k + r*8;
            uint32_t d = bufB + k*512 + ((lb_n4 ^ ((k&3)<<3)) << 2);
            CP_ASYNC16(d, &B[(size_t)(k0 + k) * LDB + colB0 + lb_n4]);
        }
        CP_COMMIT();
    };

    issue(0);
    issue(1);

    for (int s = 0; s < NIT; s++) {
        if (s + 2 < NIT) CP_WAIT1(); else CP_WAIT0();
        __syncthreads();                 // stage s visible; all warps done stage s-1
        if (s + 2 < NIT) issue(s + 2);   // overwrites (s-1)%3: safe after sync

        const float* bufA = smf + (s % GSTAGES) * 4096;
        const float* bufB = bufA + 2048;

        #pragma unroll
        for (int kk = 0; kk < 2; kk++) {
            const int kb = kk * 8;
            uint32_t a[2][4];
            #pragma unroll
            for (int i = 0; i < 2; i++) {
                int row = wm + i*16 + g;
                int sw = ((row >> 1) & 3) << 2;      // same for row and row+8
                a[i][0] = f2tf32(bufA[ row     *16 + ((kb + q4    ) ^ sw)]);
                a[i][1] = f2tf32(bufA[(row + 8)*16 + ((kb + q4    ) ^ sw)]);
                a[i][2] = f2tf32(bufA[ row     *16 + ((kb + q4 + 4) ^ sw)]);
                a[i][3] = f2tf32(bufA[(row + 8)*16 + ((kb + q4 + 4) ^ sw)]);
            }
            const int swb = q4 << 3;                 // (k&3)==q4 for both k rows
            #pragma unroll
            for (int j = 0; j < 8; j++) {
                int n = wn + j*8 + g;
                uint32_t b2[2];
                b2[0] = f2tf32(bufB[(kb + q4    )*128 + (n ^ swb)]);
                b2[1] = f2tf32(bufB[(kb + q4 + 4)*128 + (n ^ swb)]);
                mma_tf32(acc[0][j], a[0], b2);
                mma_tf32(acc[1][j], a[1], b2);
            }
        }
    }

    // epilogue
    #pragma unroll
    for (int i = 0; i < 2; i++) {
        #pragma unroll
        for (int j = 0; j < 8; j++) {
            #pragma unroll
            for (int half = 0; half < 2; half++) {
                int row = rowA0 + wm + i*16 + g + half*8;
                int col = colB0 + wn + j*8 + 2*q4;
                float v0 = acc[i][j][half*2], v1 = acc[i][j][half*2+1];
                if (SCATTER) {
                    int which = col >> 10, h = (col >> 6) & 15, d = col & 63;
                    int bb = row >> 11, t = row & (NT - 1);
                    uint32_t* dst = (which == 0) ? g_Q : (which == 1) ? g_K : g_V;
                    float sc = (which == 0) ? 0.125f : 1.0f;
                    uint2 u = make_uint2(f2tf32(v0 * sc), f2tf32(v1 * sc));
                    *(uint2*)&dst[(((size_t)(bb*NH + h) * NT + t) << 6) + d] = u;
                } else {
                    *(float2*)&C[(size_t)row * NC + col] = make_float2(v0, v1);
                }
            }
        }
    }
}

// ===========================================================================
// Flash attention, mma.sync tf32, cp.async double-buffered K/V.
// Q/K/V arrive as tf32 bits (Q pre-scaled by 0.125) -> zero cvt on load.
// Layouts identical to R3 (bank-verified): K stride 68, V stride 72, P in sQP.
// float offsets: sQP at 0 (64*68); Kbuf(b) = 4352 + b*8960; Vbuf = Kbuf+4352.
// ===========================================================================
#define SQS 68
#define SVS 72
#define KVF (64*SQS + 64*SVS)                 // 8960 floats per buffer
#define ATTN_SMEM ((64*SQS + 2*KVF) * 4)      // 89088 B

__global__ __launch_bounds__(128) void attn_tc()
{
    extern __shared__ uint32_t sm[];
    uint32_t* sQP = sm;
    const uint32_t sb = smem_to_u32(sm);

    const int tid = threadIdx.x;
    const int lane = tid & 31, w = tid >> 5;
    const int g = lane >> 2, q4 = lane & 3;
    const int qt = blockIdx.x, bh = blockIdx.y;
    const int b = bh >> 4, h = bh & 15;
    const int q0 = qt * 64;

    const uint32_t* Qg  = g_Q + ((size_t)bh * NT + q0) * ND;
    const uint32_t* Kg0 = g_K + (size_t)bh * NT * ND;
    const uint32_t* Vg0 = g_V + (size_t)bh * NT * ND;

    // Q: straight 16B copies (already tf32, scaled)
    #pragma unroll
    for (int i = 0; i < 8; i++) {
        int idx = tid + i*128;
        int row = idx >> 4, c4 = (idx & 15) << 2;
        uint4 v = *(const uint4*)&Qg[row*ND + c4];
        sQP[row*SQS + c4 + 0] = v.x; sQP[row*SQS + c4 + 1] = v.y;
        sQP[row*SQS + c4 + 2] = v.z; sQP[row*SQS + c4 + 3] = v.w;
    }
    __syncthreads();

    // Q A-fragments (warp-local rows); frees sQP for P
    uint32_t qf[8][4];
    {
        int row = w*16 + g;
        #pragma unroll
        for (int kf = 0; kf < 8; kf++) {
            int col = kf*8 + q4;
            qf[kf][0] = sQP[row*SQS + col];
            qf[kf][1] = sQP[(row+8)*SQS + col];
            qf[kf][2] = sQP[row*SQS + col + 4];
            qf[kf][3] = sQP[(row+8)*SQS + col + 4];
        }
    }

    auto issueKV = [&](int jt) {
        const int kbuf = 4352 + (jt & 1) * KVF;
        const int vbuf = kbuf + 4352;
        const uint32_t* Kg = Kg0 + (size_t)jt*64*ND;
        const uint32_t* Vg = Vg0 + (size_t)jt*64*ND;
        #pragma unroll
        for (int i = 0; i < 8; i++) {
            int c = tid + i*128;
            int row = c >> 4, d4 = (c & 15) << 2;
            CP_ASYNC16(sb + (kbuf + row*SQS + d4) * 4, &Kg[row*ND + d4]);
            CP_ASYNC16(sb + (vbuf + row*SVS + d4) * 4, &Vg[row*ND + d4]);
        }
        CP_COMMIT();
    };

    float o[8][4];
    #pragma unroll
    for (int i = 0; i < 8; i++)
        #pragma unroll
        for (int j = 0; j < 4; j++) o[i][j] = 0.f;
    float m0 = -1e30f, m1 = -1e30f, l0 = 0.f, l1 = 0.f;

    issueKV(0);

    for (int jt = 0; jt <= qt; jt++) {
        __syncthreads();                         // all warps done with buf (jt+1)&1
        if (jt + 1 <= qt) { issueKV(jt + 1); CP_WAIT1(); }
        else              { CP_WAIT0(); }
        __syncthreads();                         // tile jt visible to all

        const uint32_t* sK = sm + 4352 + (jt & 1) * KVF;
        const uint32_t* sV = sK + 4352;

        // S = Q K^T
        float s[8][4];
        #pragma unroll
        for (int i = 0; i < 8; i++)
            #pragma unroll
            for (int j = 0; j < 4; j++) s[i][j] = 0.f;
        #pragma unroll
        for (int kf = 0; kf < 8; kf++) {
            #pragma unroll
            for (int nf = 0; nf < 8; nf++) {
                uint32_t b2[2];
                b2[0] = sK[(nf*8 + g)*SQS + kf*8 + q4];
                b2[1] = sK[(nf*8 + g)*SQS + kf*8 + q4 + 4];
                mma_tf32(s[nf], qf[kf], b2);
            }
        }

        if (jt == qt) {   // causal mask on diagonal tile
            int r0 = w*16 + g, r1 = r0 + 8;
            #pragma unroll
            for (int nf = 0; nf < 8; nf++) {
                int c = nf*8 + 2*q4;
                if (c     > r0) s[nf][0] = -1e30f;
                if (c + 1 > r0) s[nf][1] = -1e30f;
                if (c     > r1) s[nf][2] = -1e30f;
                if (c + 1 > r1) s[nf][3] = -1e30f;
            }
        }

        // online softmax (rows r0, r0+8 per thread)
        float mx0 = -1e30f, mx1 = -1e30f;
        #pragma unroll
        for (int nf = 0; nf < 8; nf++) {
            mx0 = fmaxf(mx0, fmaxf(s[nf][0], s[nf][1]));
            mx1 = fmaxf(mx1, fmaxf(s[nf][2], s[nf][3]));
        }
        mx0 = fmaxf(mx0, __shfl_xor_sync(0xffffffffu, mx0, 1));
        mx0 = fmaxf(mx0, __shfl_xor_sync(0xffffffffu, mx0, 2));
        mx1 = fmaxf(mx1, __shfl_xor_sync(0xffffffffu, mx1, 1));
        mx1 = fmaxf(mx1, __shfl_xor_sync(0xffffffffu, mx1, 2));
        float nm0 = fmaxf(m0, mx0), nm1 = fmaxf(m1, mx1);
        float c0 = __expf(m0 - nm0), c1 = __expf(m1 - nm1);
        m0 = nm0; m1 = nm1;
        float ps0 = 0.f, ps1 = 0.f;
        #pragma unroll
        for (int nf = 0; nf < 8; nf++) {
            s[nf][0] = __expf(s[nf][0] - nm0);
            s[nf][1] = __expf(s[nf][1] - nm0);
            s[nf][2] = __expf(s[nf][2] - nm1);
            s[nf][3] = __expf(s[nf][3] - nm1);
            ps0 += s[nf][0] + s[nf][1];
            ps1 += s[nf][2] + s[nf][3];
        }
        ps0 += __shfl_xor_sync(0xffffffffu, ps0, 1);
        ps0 += __shfl_xor_sync(0xffffffffu, ps0, 2);
        ps1 += __shfl_xor_sync(0xffffffffu, ps1, 1);
        ps1 += __shfl_xor_sync(0xffffffffu, ps1, 2);
        l0 = l0 * c0 + ps0;
        l1 = l1 * c1 + ps1;
        #pragma unroll
        for (int df = 0; df < 8; df++) {
            o[df][0] *= c0; o[df][1] *= c0;
            o[df][2] *= c1; o[df][3] *= c1;
        }

        // P -> warp-local rows of sQP
        __syncwarp();
        {
            int r0 = w*16 + g;
            #pragma unroll
            for (int nf = 0; nf < 8; nf++) {
                int c = nf*8 + 2*q4;
                sQP[r0*SQS + c]       = f2tf32(s[nf][0]);
                sQP[r0*SQS + c + 1]   = f2tf32(s[nf][1]);
                sQP[(r0+8)*SQS + c]   = f2tf32(s[nf][2]);
                sQP[(r0+8)*SQS + c+1] = f2tf32(s[nf][3]);
            }
        }
        __syncwarp();

        // O += P V
        #pragma unroll
        for (int kf = 0; kf < 8; kf++) {
            uint32_t a[4];
            int row = w*16 + g;
            a[0] = sQP[row*SQS + kf*8 + q4];
            a[1] = sQP[(row+8)*SQS + kf*8 + q4];
            a[2] = sQP[row*SQS + kf*8 + q4 + 4];
            a[3] = sQP[(row+8)*SQS + kf*8 + q4 + 4];
            #pragma unroll
            for (int df = 0; df < 8; df++) {
                uint32_t b2[2];
                b2[0] = sV[(kf*8 + q4)*SVS + df*8 + g];
                b2[1] = sV[(kf*8 + q4 + 4)*SVS + df*8 + g];
                mma_tf32(o[df], a, b2);
            }
        }
    }

    // normalize and write to g_AO [B,T,C]
    float i0 = 1.f / l0, i1 = 1.f / l1;
    int r0 = q0 + w*16 + g;
    #pragma unroll
    for (int df = 0; df < 8; df++) {
        int col = h*ND + df*8 + 2*q4;
        *(float2*)&g_AO[(size_t)(b*NT + r0) * NC + col] =
            make_float2(o[df][0]*i0, o[df][1]*i0);
        *(float2*)&g_AO[(size_t)(b*NT + r0 + 8) * NC + col] =
            make_float2(o[df][2]*i1, o[df][3]*i1);
    }
}

// ---------------------------------------------------------------------------
extern "C" void kernel_launch(void* const* d_in, const int* in_sizes, int n_in,
                              void* d_out, int out_size)
{
    const float* x    = (const float*)d_in[0];
    const float* Wqkv = (const float*)d_in[1];
    const float* Wout = (const float*)d_in[2];
    // mask is deterministic tril -> hard-coded causal
    float* out = (float*)d_out;

    cudaFuncSetAttribute(gemm_tc<3*NC, true, false>,
                         cudaFuncAttributeMaxDynamicSharedMemorySize, GEMM_SMEM);
    cudaFuncSetAttribute(gemm_tc<NC, false, true>,
                         cudaFuncAttributeMaxDynamicSharedMemorySize, GEMM_SMEM);
    cudaFuncSetAttribute(attn_tc,
                         cudaFuncAttributeMaxDynamicSharedMemorySize, ATTN_SMEM);

    dim3 g1(3*NC / 128, NM / 128);   // 24 x 64
    gemm_tc<3*NC, true, false><<<g1, 256, GEMM_SMEM>>>(x, Wqkv, nullptr);

    dim3 ga(NT / 64, NB * NH);       // 32 x 64
    attn_tc<<<ga, 128, ATTN_SMEM>>>();

    dim3 g2(NC / 128, NM / 128);     // 8 x 64
    gemm_tc<NC, false, true><<<g2, 256, GEMM_SMEM>>>(nullptr, Wout, out);
}

// round 10
// speedup vs baseline: 4.2727x; 1.3336x over previous
#include <cuda_runtime.h>
#include <cuda_fp16.h>
#include <cstdint>

#define NB 4
#define NT 2048
#define NC 1024
#define NH 16
#define ND 64
#define NM (NB*NT)           // 8192 rows

// Scratch (allocation-free). Q/K/V fp16 (Q pre-scaled by 0.125); AO fp32.
__device__ __align__(16) __half g_Qh[(size_t)NB*NH*NT*ND];
__device__ __align__(16) __half g_Kh[(size_t)NB*NH*NT*ND];
__device__ __align__(16) __half g_Vh[(size_t)NB*NH*NT*ND];
__device__ __align__(16) float  g_AO[(size_t)NM*NC];

// ===========================================================================
// helpers
// ===========================================================================
__device__ __forceinline__ uint32_t smem_to_u32(const void* p) {
    uint32_t a;
    asm("{ .reg .u64 t; cvta.to.shared.u64 t, %1; cvt.u32.u64 %0, t; }"
        : "=r"(a) : "l"(p));
    return a;
}
__device__ __forceinline__ uint32_t f2tf32(float f) {
    uint32_t r; asm("cvt.rna.tf32.f32 %0, %1;" : "=r"(r) : "f"(f)); return r;
}
__device__ __forceinline__ uint32_t h2pack(float lo, float hi) {
    uint32_t r;
    asm("cvt.rn.f16x2.f32 %0, %1, %2;" : "=r"(r) : "f"(hi), "f"(lo));
    return r;
}
__device__ __forceinline__ void mma_tf32(float* d, const uint32_t* a, const uint32_t* b) {
    asm volatile(
        "mma.sync.aligned.m16n8k8.row.col.f32.tf32.tf32.f32 "
        "{%0,%1,%2,%3}, {%4,%5,%6,%7}, {%8,%9}, {%0,%1,%2,%3};\n"
        : "+f"(d[0]), "+f"(d[1]), "+f"(d[2]), "+f"(d[3])
        : "r"(a[0]), "r"(a[1]), "r"(a[2]), "r"(a[3]), "r"(b[0]), "r"(b[1]));
}
__device__ __forceinline__ void mma_f16(float* d, const uint32_t* a, const uint32_t* b) {
    asm volatile(
        "mma.sync.aligned.m16n8k16.row.col.f32.f16.f16.f32 "
        "{%0,%1,%2,%3}, {%4,%5,%6,%7}, {%8,%9}, {%0,%1,%2,%3};\n"
        : "+f"(d[0]), "+f"(d[1]), "+f"(d[2]), "+f"(d[3])
        : "r"(a[0]), "r"(a[1]), "r"(a[2]), "r"(a[3]), "r"(b[0]), "r"(b[1]));
}
#define LDSM_X4(R0,R1,R2,R3,A) \
    asm volatile("ldmatrix.sync.aligned.m8n8.x4.shared.b16 {%0,%1,%2,%3}, [%4];" \
        : "=r"(R0),"=r"(R1),"=r"(R2),"=r"(R3) : "r"(A))
#define LDSM_X4_T(R0,R1,R2,R3,A) \
    asm volatile("ldmatrix.sync.aligned.m8n8.x4.trans.shared.b16 {%0,%1,%2,%3}, [%4];" \
        : "=r"(R0),"=r"(R1),"=r"(R2),"=r"(R3) : "r"(A))
#define CP_ASYNC16(dst, src) \
    asm volatile("cp.async.cg.shared.global [%0], [%1], 16;" \
        :: "r"(dst), "l"(src) : "memory")
#define CP_COMMIT() asm volatile("cp.async.commit_group;" ::: "memory")
#define CP_WAIT1()  asm volatile("cp.async.wait_group 1;" ::: "memory")
#define CP_WAIT0()  asm volatile("cp.async.wait_group 0;" ::: "memory")

// ===========================================================================
// R5-PROVEN tf32 mma.sync GEMM, cp.async 3-stage pipeline (unchanged math).
// Block 128x128, BK=16, 256 threads (8 warps 4x2), warp tile 32x64.
// Only the SCATTER epilogue differs from R5: emits packed f16x2 to __half QKV.
// ===========================================================================
#define GSTAGES 3
#define GEMM_SMEM (GSTAGES * 16384)

template<int LDB, bool SCATTER, bool USE_GAO>
__global__ __launch_bounds__(256) void gemm_tc(
    const float* __restrict__ Ain, const float* __restrict__ B, float* __restrict__ C)
{
    extern __shared__ float smf[];
    const uint32_t sb = smem_to_u32(smf);
    const float* __restrict__ A = USE_GAO ? (const float*)g_AO : Ain;

    const int tid  = threadIdx.x;
    const int lane = tid & 31, wid = tid >> 5;
    const int wm = (wid & 3) * 32, wn = (wid >> 2) * 64;
    const int g = lane >> 2, q4 = lane & 3;
    const int rowA0 = blockIdx.y * 128, colB0 = blockIdx.x * 128;

    const int la_row = tid >> 2, la_k4 = (tid & 3) << 2;
    const int lb_k   = tid >> 5, lb_n4 = (tid & 31) << 2;

    float acc[2][8][4];
    #pragma unroll
    for (int i = 0; i < 2; i++)
        #pragma unroll
        for (int j = 0; j < 8; j++)
            #pragma unroll
            for (int k = 0; k < 4; k++) acc[i][j][k] = 0.f;

    constexpr int NIT = NC / 16;

    auto issue = [&](int s) {
        const uint32_t bufA = sb + (s % GSTAGES) * 16384;
        const uint32_t bufB = bufA + 8192;
        const int k0 = s * 16;
        #pragma unroll
        for (int r = 0; r < 2; r++) {
            int row = la_row + r*64;
            uint32_t d = bufA + row*64 + ((la_k4 ^ (((row>>1)&3)<<2)) << 2);
            CP_ASYNC16(d, &A[(size_t)(rowA0 + row) * NC + k0 + la_k4]);
        }
        #pragma unroll
        for (int r = 0; r < 2; r++) {
            int k = lb_k + r*8;
            uint32_t d = bufB + k*512 + ((lb_n4 ^ ((k&3)<<3)) << 2);
            CP_ASYNC16(d, &B[(size_t)(k0 + k) * LDB + colB0 + lb_n4]);
        }
        CP_COMMIT();
    };

    issue(0);
    issue(1);

    for (int s = 0; s < NIT; s++) {
        if (s + 2 < NIT) CP_WAIT1(); else CP_WAIT0();
        __syncthreads();
        if (s + 2 < NIT) issue(s + 2);

        const float* bufA = smf + (s % GSTAGES) * 4096;
        const float* bufB = bufA + 2048;

        #pragma unroll
        for (int kk = 0; kk < 2; kk++) {
            const int kb = kk * 8;
            uint32_t a[2][4];
            #pragma unroll
            for (int i = 0; i < 2; i++) {
                int row = wm + i*16 + g;
                int sw = ((row >> 1) & 3) << 2;
                a[i][0] = f2tf32(bufA[ row     *16 + ((kb + q4    ) ^ sw)]);
                a[i][1] = f2tf32(bufA[(row + 8)*16 + ((kb + q4    ) ^ sw)]);
                a[i][2] = f2tf32(bufA[ row     *16 + ((kb + q4 + 4) ^ sw)]);
                a[i][3] = f2tf32(bufA[(row + 8)*16 + ((kb + q4 + 4) ^ sw)]);
            }
            const int swb = q4 << 3;
            #pragma unroll
            for (int j = 0; j < 8; j++) {
                int n = wn + j*8 + g;
                uint32_t b2[2];
                b2[0] = f2tf32(bufB[(kb + q4    )*128 + (n ^ swb)]);
                b2[1] = f2tf32(bufB[(kb + q4 + 4)*128 + (n ^ swb)]);
                mma_tf32(acc[0][j], a[0], b2);
                mma_tf32(acc[1][j], a[1], b2);
            }
        }
    }

    // epilogue
    #pragma unroll
    for (int i = 0; i < 2; i++) {
        #pragma unroll
        for (int j = 0; j < 8; j++) {
            #pragma unroll
            for (int half = 0; half < 2; half++) {
                int row = rowA0 + wm + i*16 + g + half*8;
                int col = colB0 + wn + j*8 + 2*q4;
                float v0 = acc[i][j][half*2], v1 = acc[i][j][half*2+1];
                if (SCATTER) {
                    int which = col >> 10, h = (col >> 6) & 15, d = col & 63;
                    int bb = row >> 11, t = row & (NT - 1);
                    __half* dst = (which == 0) ? g_Qh : (which == 1) ? g_Kh : g_Vh;
                    float sc = (which == 0) ? 0.125f : 1.0f;
                    *(uint32_t*)&dst[(((size_t)(bb*NH + h) * NT + t) << 6) + d] =
                        h2pack(v0 * sc, v1 * sc);
                } else {
                    *(float2*)&C[(size_t)row * NC + col] = make_float2(v0, v1);
                }
            }
        }
    }
}

// ===========================================================================
// Flash attention, fp16 mma + ldmatrix (under test). 128 threads (4 warps),
// q-tile 64. Q 8KB + double-buffered K/V (2 x 16KB) = 40KB, all SW128.
// P stays in registers (C-frag -> f16x2 -> A-frag). Output: fp32 g_AO.
// ===========================================================================
#define ATTN_SMEM (8192 + 2*16384)
#define SWC(c, lg) ((uint32_t)(((c) ^ (lg)) << 4))

__global__ __launch_bounds__(128) void attn_f16()
{
    extern __shared__ char smc[];
    const uint32_t sb = smem_to_u32(smc);

    const int tid = threadIdx.x;
    const int lane = tid & 31, w = tid >> 5;
    const int g = lane >> 2, q4 = lane & 3;
    const int lg = lane & 7, l8 = (lane >> 3) & 1, l16 = lane >> 4;
    const int qt = blockIdx.x, bh = blockIdx.y;
    const int b = bh >> 4, h = bh & 15;
    const int q0 = qt * 64;

    const __half* Qg  = g_Qh + ((size_t)bh * NT + q0) * ND;
    const __half* Kg0 = g_Kh + (size_t)bh * NT * ND;
    const __half* Vg0 = g_Vh + (size_t)bh * NT * ND;

    const int ld_row = tid >> 3, ld_c = tid & 7;   // 16 rows x 8 chunks per 128

    // Q tile -> smem [t][d] SW128 (4 cp.async per thread)
    #pragma unroll
    for (int r = 0; r < 4; r++) {
        int row = ld_row + r * 16;
        CP_ASYNC16(sb + row*128 + SWC(ld_c, row & 7), &Qg[row*ND + ld_c*8]);
    }
    CP_COMMIT();
    CP_WAIT0();
    __syncthreads();

    // Q A-fragments (rows w*16..w*16+15, 4 k16-chunks)
    uint32_t qf[4][4];
    {
        uint32_t qRow = sb + (w*16 + lg + l8*8) * 128;
        #pragma unroll
        for (int kc = 0; kc < 4; kc++)
            LDSM_X4(qf[kc][0], qf[kc][1], qf[kc][2], qf[kc][3],
                    qRow + SWC(2*kc + l16, lg));
    }
    __syncthreads();

    // per-lane row-byte offsets for K (B-frag) and V (trans B-frag)
    uint32_t kRow[4], vRow[4];
    #pragma unroll
    for (int ng = 0; ng < 4; ng++) kRow[ng] = (ng*16 + lg + l16*8) * 128;
    #pragma unroll
    for (int kc = 0; kc < 4; kc++) vRow[kc] = (kc*16 + lg + l8*8) * 128;

    auto issueKV = [&](int jt) {
        const uint32_t kb = sb + 8192 + (jt & 1) * 16384;
        const uint32_t vb = kb + 8192;
        const __half* Kg = Kg0 + (size_t)jt*64*ND;
        const __half* Vg = Vg0 + (size_t)jt*64*ND;
        #pragma unroll
        for (int r = 0; r < 4; r++) {
            int row = ld_row + r * 16;
            uint32_t swo = row*128 + SWC(ld_c, row & 7);
            CP_ASYNC16(kb + swo, &Kg[row*ND + ld_c*8]);
            CP_ASYNC16(vb + swo, &Vg[row*ND + ld_c*8]);
        }
        CP_COMMIT();
    };

    float o[8][4];
    #pragma unroll
    for (int i = 0; i < 8; i++)
        #pragma unroll
        for (int j = 0; j < 4; j++) o[i][j] = 0.f;
    float m0 = -1e30f, m1 = -1e30f, l0 = 0.f, l1 = 0.f;

    issueKV(0);

    for (int jt = 0; jt <= qt; jt++) {
        __syncthreads();                          // all warps done with this buffer
        if (jt + 1 <= qt) { issueKV(jt + 1); CP_WAIT1(); }
        else              { CP_WAIT0(); }
        __syncthreads();

        const uint32_t kb = sb + 8192 + (jt & 1) * 16384;
        const uint32_t vb = kb + 8192;

        // S = Q K^T : s[nf] covers kv cols nf*8..nf*8+7
        float s[8][4];
        #pragma unroll
        for (int i = 0; i < 8; i++)
            #pragma unroll
            for (int j = 0; j < 4; j++) s[i][j] = 0.f;
        #pragma unroll
        for (int kc = 0; kc < 4; kc++) {          // d chunks of 16
            #pragma unroll
            for (int ng = 0; ng < 4; ng++) {      // kv-position groups of 16
                uint32_t b0, b1, b2, b3;
                LDSM_X4(b0, b1, b2, b3, kb + kRow[ng] + SWC(2*kc + l8, lg));
                uint32_t bl[2] = {b0, b1}, bhh[2] = {b2, b3};
                mma_f16(s[2*ng],   qf[kc], bl);
                mma_f16(s[2*ng+1], qf[kc], bhh);
            }
        }

        // causal mask on diagonal tile
        if (jt == qt) {
            int r0 = w*16 + g, r1 = r0 + 8;
            #pragma unroll
            for (int nf = 0; nf < 8; nf++) {
                int c = nf*8 + 2*q4;
                if (c     > r0) s[nf][0] = -1e30f;
                if (c + 1 > r0) s[nf][1] = -1e30f;
                if (c     > r1) s[nf][2] = -1e30f;
                if (c + 1 > r1) s[nf][3] = -1e30f;
            }
        }

        // online softmax (rows r0, r0+8 per thread, spread over 4 lanes)
        float mx0 = -1e30f, mx1 = -1e30f;
        #pragma unroll
        for (int nf = 0; nf < 8; nf++) {
            mx0 = fmaxf(mx0, fmaxf(s[nf][0], s[nf][1]));
            mx1 = fmaxf(mx1, fmaxf(s[nf][2], s[nf][3]));
        }
        mx0 = fmaxf(mx0, __shfl_xor_sync(0xffffffffu, mx0, 1));
        mx0 = fmaxf(mx0, __shfl_xor_sync(0xffffffffu, mx0, 2));
        mx1 = fmaxf(mx1, __shfl_xor_sync(0xffffffffu, mx1, 1));
        mx1 = fmaxf(mx1, __shfl_xor_sync(0xffffffffu, mx1, 2));
        float nm0 = fmaxf(m0, mx0), nm1 = fmaxf(m1, mx1);
        float c0 = __expf(m0 - nm0), c1 = __expf(m1 - nm1);
        m0 = nm0; m1 = nm1;
        float ps0 = 0.f, ps1 = 0.f;
        #pragma unroll
        for (int nf = 0; nf < 8; nf++) {
            s[nf][0] = __expf(s[nf][0] - nm0);
            s[nf][1] = __expf(s[nf][1] - nm0);
            s[nf][2] = __expf(s[nf][2] - nm1);
            s[nf][3] = __expf(s[nf][3] - nm1);
            ps0 += s[nf][0] + s[nf][1];
            ps1 += s[nf][2] + s[nf][3];
        }
        ps0 += __shfl_xor_sync(0xffffffffu, ps0, 1);
        ps0 += __shfl_xor_sync(0xffffffffu, ps0, 2);
        ps1 += __shfl_xor_sync(0xffffffffu, ps1, 1);
        ps1 += __shfl_xor_sync(0xffffffffu, ps1, 2);
        l0 = l0 * c0 + ps0;
        l1 = l1 * c1 + ps1;
        #pragma unroll
        for (int df = 0; df < 8; df++) {
            o[df][0] *= c0; o[df][1] *= c0;
            o[df][2] *= c1; o[df][3] *= c1;
        }

        // P: C-frag -> f16 A-frags, registers only
        uint32_t p[4][4];
        #pragma unroll
        for (int kc = 0; kc < 4; kc++) {
            p[kc][0] = h2pack(s[2*kc][0],   s[2*kc][1]);
            p[kc][1] = h2pack(s[2*kc][2],   s[2*kc][3]);
            p[kc][2] = h2pack(s[2*kc+1][0], s[2*kc+1][1]);
            p[kc][3] = h2pack(s[2*kc+1][2], s[2*kc+1][3]);
        }

        // O += P V  (V via ldmatrix.trans)
        #pragma unroll
        for (int kc = 0; kc < 4; kc++) {          // kv-position chunks of 16
            #pragma unroll
            for (int dg = 0; dg < 4; dg++) {      // d groups of 16
                uint32_t v0, v1, v2, v3;
                LDSM_X4_T(v0, v1, v2, v3, vb + vRow[kc] + SWC(2*dg + l16, lg));
                uint32_t bl[2] = {v0, v1}, bhh[2] = {v2, v3};
                mma_f16(o[2*dg],   p[kc], bl);
                mma_f16(o[2*dg+1], p[kc], bhh);
            }
        }
    }

    // normalize, write fp32 to g_AO [B,T,C]
    float i0 = 1.f / l0, i1 = 1.f / l1;
    int r0 = q0 + w*16 + g;
    #pragma unroll
    for (int df = 0; df < 8; df++) {
        int col = h*ND + df*8 + 2*q4;
        *(float2*)&g_AO[(size_t)(b*NT + r0) * NC + col] =
            make_float2(o[df][0]*i0, o[df][1]*i0);
        *(float2*)&g_AO[(size_t)(b*NT + r0 + 8) * NC + col] =
            make_float2(o[df][2]*i1, o[df][3]*i1);
    }
}

// ---------------------------------------------------------------------------
extern "C" void kernel_launch(void* const* d_in, const int* in_sizes, int n_in,
                              void* d_out, int out_size)
{
    const float* x    = (const float*)d_in[0];
    const float* Wqkv = (const float*)d_in[1];
    const float* Wout = (const float*)d_in[2];
    // mask is deterministic tril -> hard-coded causal
    float* out = (float*)d_out;

    cudaFuncSetAttribute(gemm_tc<3*NC, true, false>,
                         cudaFuncAttributeMaxDynamicSharedMemorySize, GEMM_SMEM);
    cudaFuncSetAttribute(gemm_tc<NC, false, true>,
                         cudaFuncAttributeMaxDynamicSharedMemorySize, GEMM_SMEM);
    cudaFuncSetAttribute(attn_f16,
                         cudaFuncAttributeMaxDynamicSharedMemorySize, ATTN_SMEM);

    dim3 g1(3*NC / 128, NM / 128);   // 24 x 64
    gemm_tc<3*NC, true, false><<<g1, 256, GEMM_SMEM>>>(x, Wqkv, nullptr);

    dim3 ga(NT / 64, NB * NH);       // 32 x 64
    attn_f16<<<ga, 128, ATTN_SMEM>>>();

    dim3 g2(NC / 128, NM / 128);     // 8 x 64
    gemm_tc<NC, false, true><<<g2, 256, GEMM_SMEM>>>(nullptr, Wout, out);
}